// round 14
// baseline (speedup 1.0000x reference)
#include <cuda_runtime.h>
#include <math.h>

// ---------------------------------------------------------------------------
// FluidFlow: g <- (g + (2/(W(1+g)+1) - 1)*DT) * mask, `steps` times.
// Identity: reference's z = exp(xi^2/2 + c1 - 1) == 1+g exactly, so the step
// is the elementwise map g += (2/(1+W(1+g)) - 1)*DT, mask at the end.
//
// Round 9 was MUFU-pipe-bound (2 lg2/elem-step, ~97% of xu peak). Fix: the
// whole 20-step evolution is a smooth scalar function F(g0) on [0,1). Build
// F as a 4096-interval table (tiny init kernel doing the accurate W
// iteration at 4098 nodes), then apply with one lerp per element from a
// shared-memory copy. Main kernel becomes HBM-streaming-bound.
// ---------------------------------------------------------------------------

#define TABN 4096
#define TPB  256

__device__ __forceinline__ float lg2f(float x) {
    float y; asm("lg2.approx.f32 %0, %1;" : "=f"(y) : "f"(x)); return y;
}
__device__ __forceinline__ float rcpf(float x) {
    float y; asm("rcp.approx.f32 %0, %1;" : "=f"(y) : "f"(x)); return y;
}

#define LN2F 0.69314718f

// W(z) for z in [1, ~2.1]: cubic seed in L = ln z about L=0 (w(0)=Omega),
// then 3 log-form Newton steps -> fp32-exact.
__device__ __forceinline__ float lambertw_z(float z) {
    float L = LN2F * lg2f(z);
    float w = 0.56714329f + L * (0.36189625f + L * (0.07367770f + L * (-0.00134260f)));
    #pragma unroll
    for (int i = 0; i < 3; ++i) {
        float s0 = rcpf(w + 1.0f);
        float f  = fmaf(LN2F, lg2f(w), w) - L;   // f = w + ln(w) - L
        w = fmaf(-f * w, s0, w);
    }
    return w;
}

// Evolve one scalar through `steps` Euler steps (full-accuracy W each step;
// only runs on 4098 table nodes so cost is irrelevant).
__device__ float evolve_node(float g, int steps) {
    for (int k = 0; k < steps; ++k) {
        float w = lambertw_z(g + 1.0f);
        float s = rcpf(w + 1.0f);
        float u = fmaf(w, s, s - 1.0f);          // NR: s = 1/(1+w) exact
        s = fmaf(-s, u, s);
        g = fmaf(0.02f, s, g - 0.01f);           // g += (2s-1)*0.01
    }
    return g;
}

// Table: d_tab[j] = ( F(j/TABN), F((j+1)/TABN) - F(j/TABN) ), j = 0..TABN+1.
// Covers indices up to 4096 (guards against round-up of g*TABN at g -> 1).
__device__ float2 d_tab[TABN + 2];

__global__ void build_table_kernel(const int* __restrict__ stepsp) {
    int j = blockIdx.x * blockDim.x + threadIdx.x;
    if (j >= TABN + 2) return;
    int steps = *stepsp;
    float f0 = evolve_node((float)j       * (1.0f / TABN), steps);
    float f1 = evolve_node((float)(j + 1) * (1.0f / TABN), steps);
    d_tab[j] = make_float2(f0, f1 - f0);
}

// Main streaming kernel. Row-strided over blocks (no integer division for
// the boundary mask); table staged once per block into smem.
__global__ void __launch_bounds__(TPB)
apply_table_vec4(const float4* __restrict__ in4, float4* __restrict__ out4,
                 int N, int nrowvec) {
    __shared__ float2 stab[TABN + 2];
    for (int i = threadIdx.x; i < TABN + 2; i += TPB) stab[i] = d_tab[i];
    __syncthreads();

    for (int row = blockIdx.x; row < N; row += gridDim.x) {
        bool rowin = (row > 0) && (row < N - 1);
        int rbase = row * nrowvec;
        for (int vc = threadIdx.x; vc < nrowvec; vc += TPB) {
            float4 g4 = in4[rbase + vc];
            float r[4] = {g4.x, g4.y, g4.z, g4.w};
            #pragma unroll
            for (int i = 0; i < 4; ++i) {
                float f   = r[i] * (float)TABN;
                int   idx = (int)f;
                float fr  = f - (float)idx;
                float2 tv = stab[idx];
                r[i] = fmaf(fr, tv.y, tv.x);
            }
            if (!rowin) {
                r[0] = r[1] = r[2] = r[3] = 0.0f;
            } else {
                if (vc == 0)           r[0] = 0.0f;   // col 0
                if (vc == nrowvec - 1) r[3] = 0.0f;   // col N-1
            }
            out4[rbase + vc] = make_float4(r[0], r[1], r[2], r[3]);
        }
    }
}

// Generic scalar fallback (only if N % 4 != 0; never for N=6144).
__global__ void apply_table_scalar(const float* __restrict__ gin,
                                   float* __restrict__ gout,
                                   int N, int total) {
    __shared__ float2 stab[TABN + 2];
    for (int i = threadIdx.x; i < TABN + 2; i += blockDim.x) stab[i] = d_tab[i];
    __syncthreads();
    for (int idx = blockIdx.x * blockDim.x + threadIdx.x; idx < total;
         idx += gridDim.x * blockDim.x) {
        int row = idx / N, col = idx - row * N;
        float g = gin[idx];
        float f = g * (float)TABN;
        int   t = (int)f;
        float fr = f - (float)t;
        float2 tv = stab[t];
        float r = fmaf(fr, tv.y, tv.x);
        bool interior = (row > 0) && (row < N - 1) && (col > 0) && (col < N - 1);
        gout[idx] = interior ? r : 0.0f;
    }
}

extern "C" void kernel_launch(void* const* d_in, const int* in_sizes, int n_in,
                              void* d_out, int out_size) {
    const float* gin   = (const float*)d_in[0];
    const int*  stepsp = (const int*)d_in[1];
    float*      gout   = (float*)d_out;

    int total = in_sizes[0];
    int N = (int)(sqrt((double)total) + 0.5);

    // 1) Build F table (tiny; ordered before the apply kernel on the stream).
    build_table_kernel<<<(TABN + 2 + 255) / 256, 256>>>(stepsp);

    // 2) Apply.
    if ((N & 3) == 0) {
        int nrowvec = N >> 2;
        int blocks  = 148 * 6;                  // grid-strided over rows
        if (blocks > N) blocks = N;
        apply_table_vec4<<<blocks, TPB>>>((const float4*)gin, (float4*)gout,
                                          N, nrowvec);
    } else {
        int blocks = 148 * 6;
        apply_table_scalar<<<blocks, TPB>>>(gin, gout, N, total);
    }
}

// round 15
// speedup vs baseline: 1.0220x; 1.0220x over previous
#include <cuda_runtime.h>
#include <math.h>

// ---------------------------------------------------------------------------
// FluidFlow: g <- (g + (2/(W(1+g)+1) - 1)*DT) * mask, `steps` times.
// Identity: reference's z = exp(xi^2/2 + c1 - 1) == 1+g exactly, so the step
// is the elementwise map g += (2/(1+W(1+g)) - 1)*DT, mask at the end.
//
// Round 9 was MUFU-pipe-bound (2 lg2/elem-step, ~97% of xu peak). Fix: the
// whole 20-step evolution is a smooth scalar function F(g0) on [0,1). Build
// F as a 4096-interval table (tiny init kernel doing the accurate W
// iteration at 4098 nodes), then apply with one lerp per element from a
// shared-memory copy. Main kernel becomes HBM-streaming-bound.
// ---------------------------------------------------------------------------

#define TABN 4096
#define TPB  256

__device__ __forceinline__ float lg2f(float x) {
    float y; asm("lg2.approx.f32 %0, %1;" : "=f"(y) : "f"(x)); return y;
}
__device__ __forceinline__ float rcpf(float x) {
    float y; asm("rcp.approx.f32 %0, %1;" : "=f"(y) : "f"(x)); return y;
}

#define LN2F 0.69314718f

// W(z) for z in [1, ~2.1]: cubic seed in L = ln z about L=0 (w(0)=Omega),
// then 3 log-form Newton steps -> fp32-exact.
__device__ __forceinline__ float lambertw_z(float z) {
    float L = LN2F * lg2f(z);
    float w = 0.56714329f + L * (0.36189625f + L * (0.07367770f + L * (-0.00134260f)));
    #pragma unroll
    for (int i = 0; i < 3; ++i) {
        float s0 = rcpf(w + 1.0f);
        float f  = fmaf(LN2F, lg2f(w), w) - L;   // f = w + ln(w) - L
        w = fmaf(-f * w, s0, w);
    }
    return w;
}

// Evolve one scalar through `steps` Euler steps (full-accuracy W each step;
// only runs on 4098 table nodes so cost is irrelevant).
__device__ float evolve_node(float g, int steps) {
    for (int k = 0; k < steps; ++k) {
        float w = lambertw_z(g + 1.0f);
        float s = rcpf(w + 1.0f);
        float u = fmaf(w, s, s - 1.0f);          // NR: s = 1/(1+w) exact
        s = fmaf(-s, u, s);
        g = fmaf(0.02f, s, g - 0.01f);           // g += (2s-1)*0.01
    }
    return g;
}

// Table: d_tab[j] = ( F(j/TABN), F((j+1)/TABN) - F(j/TABN) ), j = 0..TABN+1.
// Covers indices up to 4096 (guards against round-up of g*TABN at g -> 1).
__device__ float2 d_tab[TABN + 2];

__global__ void build_table_kernel(const int* __restrict__ stepsp) {
    int j = blockIdx.x * blockDim.x + threadIdx.x;
    if (j >= TABN + 2) return;
    int steps = *stepsp;
    float f0 = evolve_node((float)j       * (1.0f / TABN), steps);
    float f1 = evolve_node((float)(j + 1) * (1.0f / TABN), steps);
    d_tab[j] = make_float2(f0, f1 - f0);
}

// Main streaming kernel. Row-strided over blocks (no integer division for
// the boundary mask); table staged once per block into smem.
__global__ void __launch_bounds__(TPB)
apply_table_vec4(const float4* __restrict__ in4, float4* __restrict__ out4,
                 int N, int nrowvec) {
    __shared__ float2 stab[TABN + 2];
    for (int i = threadIdx.x; i < TABN + 2; i += TPB) stab[i] = d_tab[i];
    __syncthreads();

    for (int row = blockIdx.x; row < N; row += gridDim.x) {
        bool rowin = (row > 0) && (row < N - 1);
        int rbase = row * nrowvec;
        for (int vc = threadIdx.x; vc < nrowvec; vc += TPB) {
            float4 g4 = in4[rbase + vc];
            float r[4] = {g4.x, g4.y, g4.z, g4.w};
            #pragma unroll
            for (int i = 0; i < 4; ++i) {
                float f   = r[i] * (float)TABN;
                int   idx = (int)f;
                float fr  = f - (float)idx;
                float2 tv = stab[idx];
                r[i] = fmaf(fr, tv.y, tv.x);
            }
            if (!rowin) {
                r[0] = r[1] = r[2] = r[3] = 0.0f;
            } else {
                if (vc == 0)           r[0] = 0.0f;   // col 0
                if (vc == nrowvec - 1) r[3] = 0.0f;   // col N-1
            }
            out4[rbase + vc] = make_float4(r[0], r[1], r[2], r[3]);
        }
    }
}

// Generic scalar fallback (only if N % 4 != 0; never for N=6144).
__global__ void apply_table_scalar(const float* __restrict__ gin,
                                   float* __restrict__ gout,
                                   int N, int total) {
    __shared__ float2 stab[TABN + 2];
    for (int i = threadIdx.x; i < TABN + 2; i += blockDim.x) stab[i] = d_tab[i];
    __syncthreads();
    for (int idx = blockIdx.x * blockDim.x + threadIdx.x; idx < total;
         idx += gridDim.x * blockDim.x) {
        int row = idx / N, col = idx - row * N;
        float g = gin[idx];
        float f = g * (float)TABN;
        int   t = (int)f;
        float fr = f - (float)t;
        float2 tv = stab[t];
        float r = fmaf(fr, tv.y, tv.x);
        bool interior = (row > 0) && (row < N - 1) && (col > 0) && (col < N - 1);
        gout[idx] = interior ? r : 0.0f;
    }
}

extern "C" void kernel_launch(void* const* d_in, const int* in_sizes, int n_in,
                              void* d_out, int out_size) {
    const float* gin   = (const float*)d_in[0];
    const int*  stepsp = (const int*)d_in[1];
    float*      gout   = (float*)d_out;

    int total = in_sizes[0];
    int N = (int)(sqrt((double)total) + 0.5);

    // 1) Build F table (tiny; ordered before the apply kernel on the stream).
    build_table_kernel<<<(TABN + 2 + 255) / 256, 256>>>(stepsp);

    // 2) Apply.
    if ((N & 3) == 0) {
        int nrowvec = N >> 2;
        int blocks  = 148 * 6;                  // grid-strided over rows
        if (blocks > N) blocks = N;
        apply_table_vec4<<<blocks, TPB>>>((const float4*)gin, (float4*)gout,
                                          N, nrowvec);
    } else {
        int blocks = 148 * 6;
        apply_table_scalar<<<blocks, TPB>>>(gin, gout, N, total);
    }
}

// round 16
// speedup vs baseline: 1.0456x; 1.0230x over previous
#include <cuda_runtime.h>
#include <math.h>

// ---------------------------------------------------------------------------
// FluidFlow: g <- (g + (2/(W(1+g)+1) - 1)*DT) * mask, `steps` times.
// Identity: reference's z = exp(xi^2/2 + c1 - 1) == 1+g exactly, so the step
// is the elementwise map g += (2/(1+W(1+g)) - 1)*DT, mask at the end.
//
// Round 9 was MUFU-pipe-bound (2 lg2/elem-step, ~97% of xu peak). Fix: the
// whole 20-step evolution is a smooth scalar function F(g0) on [0,1). Build
// F as a 4096-interval table (tiny init kernel doing the accurate W
// iteration at 4098 nodes), then apply with one lerp per element from a
// shared-memory copy. Main kernel becomes HBM-streaming-bound.
// ---------------------------------------------------------------------------

#define TABN 4096
#define TPB  256

__device__ __forceinline__ float lg2f(float x) {
    float y; asm("lg2.approx.f32 %0, %1;" : "=f"(y) : "f"(x)); return y;
}
__device__ __forceinline__ float rcpf(float x) {
    float y; asm("rcp.approx.f32 %0, %1;" : "=f"(y) : "f"(x)); return y;
}

#define LN2F 0.69314718f

// W(z) for z in [1, ~2.1]: cubic seed in L = ln z about L=0 (w(0)=Omega),
// then 3 log-form Newton steps -> fp32-exact.
__device__ __forceinline__ float lambertw_z(float z) {
    float L = LN2F * lg2f(z);
    float w = 0.56714329f + L * (0.36189625f + L * (0.07367770f + L * (-0.00134260f)));
    #pragma unroll
    for (int i = 0; i < 3; ++i) {
        float s0 = rcpf(w + 1.0f);
        float f  = fmaf(LN2F, lg2f(w), w) - L;   // f = w + ln(w) - L
        w = fmaf(-f * w, s0, w);
    }
    return w;
}

// Evolve one scalar through `steps` Euler steps (full-accuracy W each step;
// only runs on 4098 table nodes so cost is irrelevant).
__device__ float evolve_node(float g, int steps) {
    for (int k = 0; k < steps; ++k) {
        float w = lambertw_z(g + 1.0f);
        float s = rcpf(w + 1.0f);
        float u = fmaf(w, s, s - 1.0f);          // NR: s = 1/(1+w) exact
        s = fmaf(-s, u, s);
        g = fmaf(0.02f, s, g - 0.01f);           // g += (2s-1)*0.01
    }
    return g;
}

// Table: d_tab[j] = ( F(j/TABN), F((j+1)/TABN) - F(j/TABN) ), j = 0..TABN+1.
// Covers indices up to 4096 (guards against round-up of g*TABN at g -> 1).
__device__ float2 d_tab[TABN + 2];

__global__ void build_table_kernel(const int* __restrict__ stepsp) {
    int j = blockIdx.x * blockDim.x + threadIdx.x;
    if (j >= TABN + 2) return;
    int steps = *stepsp;
    float f0 = evolve_node((float)j       * (1.0f / TABN), steps);
    float f1 = evolve_node((float)(j + 1) * (1.0f / TABN), steps);
    d_tab[j] = make_float2(f0, f1 - f0);
}

// Main streaming kernel. Row-strided over blocks (no integer division for
// the boundary mask); table staged once per block into smem.
__global__ void __launch_bounds__(TPB)
apply_table_vec4(const float4* __restrict__ in4, float4* __restrict__ out4,
                 int N, int nrowvec) {
    __shared__ float2 stab[TABN + 2];
    for (int i = threadIdx.x; i < TABN + 2; i += TPB) stab[i] = d_tab[i];
    __syncthreads();

    for (int row = blockIdx.x; row < N; row += gridDim.x) {
        bool rowin = (row > 0) && (row < N - 1);
        int rbase = row * nrowvec;
        for (int vc = threadIdx.x; vc < nrowvec; vc += TPB) {
            float4 g4 = in4[rbase + vc];
            float r[4] = {g4.x, g4.y, g4.z, g4.w};
            #pragma unroll
            for (int i = 0; i < 4; ++i) {
                float f   = r[i] * (float)TABN;
                int   idx = (int)f;
                float fr  = f - (float)idx;
                float2 tv = stab[idx];
                r[i] = fmaf(fr, tv.y, tv.x);
            }
            if (!rowin) {
                r[0] = r[1] = r[2] = r[3] = 0.0f;
            } else {
                if (vc == 0)           r[0] = 0.0f;   // col 0
                if (vc == nrowvec - 1) r[3] = 0.0f;   // col N-1
            }
            out4[rbase + vc] = make_float4(r[0], r[1], r[2], r[3]);
        }
    }
}

// Generic scalar fallback (only if N % 4 != 0; never for N=6144).
__global__ void apply_table_scalar(const float* __restrict__ gin,
                                   float* __restrict__ gout,
                                   int N, int total) {
    __shared__ float2 stab[TABN + 2];
    for (int i = threadIdx.x; i < TABN + 2; i += blockDim.x) stab[i] = d_tab[i];
    __syncthreads();
    for (int idx = blockIdx.x * blockDim.x + threadIdx.x; idx < total;
         idx += gridDim.x * blockDim.x) {
        int row = idx / N, col = idx - row * N;
        float g = gin[idx];
        float f = g * (float)TABN;
        int   t = (int)f;
        float fr = f - (float)t;
        float2 tv = stab[t];
        float r = fmaf(fr, tv.y, tv.x);
        bool interior = (row > 0) && (row < N - 1) && (col > 0) && (col < N - 1);
        gout[idx] = interior ? r : 0.0f;
    }
}

extern "C" void kernel_launch(void* const* d_in, const int* in_sizes, int n_in,
                              void* d_out, int out_size) {
    const float* gin   = (const float*)d_in[0];
    const int*  stepsp = (const int*)d_in[1];
    float*      gout   = (float*)d_out;

    int total = in_sizes[0];
    int N = (int)(sqrt((double)total) + 0.5);

    // 1) Build F table (tiny; ordered before the apply kernel on the stream).
    build_table_kernel<<<(TABN + 2 + 255) / 256, 256>>>(stepsp);

    // 2) Apply.
    if ((N & 3) == 0) {
        int nrowvec = N >> 2;
        int blocks  = 148 * 6;                  // grid-strided over rows
        if (blocks > N) blocks = N;
        apply_table_vec4<<<blocks, TPB>>>((const float4*)gin, (float4*)gout,
                                          N, nrowvec);
    } else {
        int blocks = 148 * 6;
        apply_table_scalar<<<blocks, TPB>>>(gin, gout, N, total);
    }
}

// round 17
// speedup vs baseline: 1.0461x; 1.0005x over previous
#include <cuda_runtime.h>
#include <math.h>

// ---------------------------------------------------------------------------
// FluidFlow: g <- (g + (2/(W(1+g)+1) - 1)*DT) * mask, `steps` times.
// Identity: reference's z = exp(xi^2/2 + c1 - 1) == 1+g exactly, so the step
// is the elementwise map g += (2/(1+W(1+g)) - 1)*DT, mask at the end.
//
// Round 9 was MUFU-pipe-bound (2 lg2/elem-step, ~97% of xu peak). Fix: the
// whole 20-step evolution is a smooth scalar function F(g0) on [0,1). Build
// F as a 4096-interval table (tiny init kernel doing the accurate W
// iteration at 4098 nodes), then apply with one lerp per element from a
// shared-memory copy. Main kernel becomes HBM-streaming-bound.
// ---------------------------------------------------------------------------

#define TABN 4096
#define TPB  256

__device__ __forceinline__ float lg2f(float x) {
    float y; asm("lg2.approx.f32 %0, %1;" : "=f"(y) : "f"(x)); return y;
}
__device__ __forceinline__ float rcpf(float x) {
    float y; asm("rcp.approx.f32 %0, %1;" : "=f"(y) : "f"(x)); return y;
}

#define LN2F 0.69314718f

// W(z) for z in [1, ~2.1]: cubic seed in L = ln z about L=0 (w(0)=Omega),
// then 3 log-form Newton steps -> fp32-exact.
__device__ __forceinline__ float lambertw_z(float z) {
    float L = LN2F * lg2f(z);
    float w = 0.56714329f + L * (0.36189625f + L * (0.07367770f + L * (-0.00134260f)));
    #pragma unroll
    for (int i = 0; i < 3; ++i) {
        float s0 = rcpf(w + 1.0f);
        float f  = fmaf(LN2F, lg2f(w), w) - L;   // f = w + ln(w) - L
        w = fmaf(-f * w, s0, w);
    }
    return w;
}

// Evolve one scalar through `steps` Euler steps (full-accuracy W each step;
// only runs on 4098 table nodes so cost is irrelevant).
__device__ float evolve_node(float g, int steps) {
    for (int k = 0; k < steps; ++k) {
        float w = lambertw_z(g + 1.0f);
        float s = rcpf(w + 1.0f);
        float u = fmaf(w, s, s - 1.0f);          // NR: s = 1/(1+w) exact
        s = fmaf(-s, u, s);
        g = fmaf(0.02f, s, g - 0.01f);           // g += (2s-1)*0.01
    }
    return g;
}

// Table: d_tab[j] = ( F(j/TABN), F((j+1)/TABN) - F(j/TABN) ), j = 0..TABN+1.
// Covers indices up to 4096 (guards against round-up of g*TABN at g -> 1).
__device__ float2 d_tab[TABN + 2];

__global__ void build_table_kernel(const int* __restrict__ stepsp) {
    int j = blockIdx.x * blockDim.x + threadIdx.x;
    if (j >= TABN + 2) return;
    int steps = *stepsp;
    float f0 = evolve_node((float)j       * (1.0f / TABN), steps);
    float f1 = evolve_node((float)(j + 1) * (1.0f / TABN), steps);
    d_tab[j] = make_float2(f0, f1 - f0);
}

// Main streaming kernel. Row-strided over blocks (no integer division for
// the boundary mask); table staged once per block into smem.
__global__ void __launch_bounds__(TPB)
apply_table_vec4(const float4* __restrict__ in4, float4* __restrict__ out4,
                 int N, int nrowvec) {
    __shared__ float2 stab[TABN + 2];
    for (int i = threadIdx.x; i < TABN + 2; i += TPB) stab[i] = d_tab[i];
    __syncthreads();

    for (int row = blockIdx.x; row < N; row += gridDim.x) {
        bool rowin = (row > 0) && (row < N - 1);
        int rbase = row * nrowvec;
        for (int vc = threadIdx.x; vc < nrowvec; vc += TPB) {
            float4 g4 = in4[rbase + vc];
            float r[4] = {g4.x, g4.y, g4.z, g4.w};
            #pragma unroll
            for (int i = 0; i < 4; ++i) {
                float f   = r[i] * (float)TABN;
                int   idx = (int)f;
                float fr  = f - (float)idx;
                float2 tv = stab[idx];
                r[i] = fmaf(fr, tv.y, tv.x);
            }
            if (!rowin) {
                r[0] = r[1] = r[2] = r[3] = 0.0f;
            } else {
                if (vc == 0)           r[0] = 0.0f;   // col 0
                if (vc == nrowvec - 1) r[3] = 0.0f;   // col N-1
            }
            out4[rbase + vc] = make_float4(r[0], r[1], r[2], r[3]);
        }
    }
}

// Generic scalar fallback (only if N % 4 != 0; never for N=6144).
__global__ void apply_table_scalar(const float* __restrict__ gin,
                                   float* __restrict__ gout,
                                   int N, int total) {
    __shared__ float2 stab[TABN + 2];
    for (int i = threadIdx.x; i < TABN + 2; i += blockDim.x) stab[i] = d_tab[i];
    __syncthreads();
    for (int idx = blockIdx.x * blockDim.x + threadIdx.x; idx < total;
         idx += gridDim.x * blockDim.x) {
        int row = idx / N, col = idx - row * N;
        float g = gin[idx];
        float f = g * (float)TABN;
        int   t = (int)f;
        float fr = f - (float)t;
        float2 tv = stab[t];
        float r = fmaf(fr, tv.y, tv.x);
        bool interior = (row > 0) && (row < N - 1) && (col > 0) && (col < N - 1);
        gout[idx] = interior ? r : 0.0f;
    }
}

extern "C" void kernel_launch(void* const* d_in, const int* in_sizes, int n_in,
                              void* d_out, int out_size) {
    const float* gin   = (const float*)d_in[0];
    const int*  stepsp = (const int*)d_in[1];
    float*      gout   = (float*)d_out;

    int total = in_sizes[0];
    int N = (int)(sqrt((double)total) + 0.5);

    // 1) Build F table (tiny; ordered before the apply kernel on the stream).
    build_table_kernel<<<(TABN + 2 + 255) / 256, 256>>>(stepsp);

    // 2) Apply.
    if ((N & 3) == 0) {
        int nrowvec = N >> 2;
        int blocks  = 148 * 6;                  // grid-strided over rows
        if (blocks > N) blocks = N;
        apply_table_vec4<<<blocks, TPB>>>((const float4*)gin, (float4*)gout,
                                          N, nrowvec);
    } else {
        int blocks = 148 * 6;
        apply_table_scalar<<<blocks, TPB>>>(gin, gout, N, total);
    }
}